// round 12
// baseline (speedup 1.0000x reference)
#include <cuda_runtime.h>
#include <cuda_fp16.h>

#define NB 4
#define NS 2048
#define ND 1024
#define NH 16
#define HD 64
#define NEGV (-10000.0f)
#define SCALE 0.125f
#define SROW 2052   // fp32 score row stride; %32==4 conflict-free, %4==0 for float4

// ---------------- scratch (static device arrays; no runtime allocation) ------------
__device__ float g_qh[NB * NH * NS * HD];
__device__ float g_kh[NB * NH * NS * HD];
__device__ float g_vh[NB * NH * NS * HD];
__device__ float g_ao[NB * NS * ND];

// ---------------- helpers ----------------------------------------------------------
__device__ __forceinline__ unsigned f2tf(float x) {
    unsigned u; asm("cvt.rna.tf32.f32 %0, %1;" : "=r"(u) : "f"(x)); return u;
}
__device__ __forceinline__ float f2tff(float x) { return __uint_as_float(f2tf(x)); }

__device__ __forceinline__ unsigned packh2(float x, float y) {
    __half2 h = __floats2half2_rn(x, y);
    return *reinterpret_cast<unsigned*>(&h);
}

__device__ __forceinline__ void mma_tf32(float c[4], const unsigned a[4], const unsigned b[2]) {
    asm volatile(
        "mma.sync.aligned.m16n8k8.row.col.f32.tf32.tf32.f32 "
        "{%0,%1,%2,%3}, {%4,%5,%6,%7}, {%8,%9}, {%0,%1,%2,%3};"
        : "+f"(c[0]), "+f"(c[1]), "+f"(c[2]), "+f"(c[3])
        : "r"(a[0]), "r"(a[1]), "r"(a[2]), "r"(a[3]), "r"(b[0]), "r"(b[1]));
}

__device__ __forceinline__ void mma_f16(float c[4], const unsigned a[4], const unsigned b[2]) {
    asm volatile(
        "mma.sync.aligned.m16n8k16.row.col.f32.f16.f16.f32 "
        "{%0,%1,%2,%3}, {%4,%5,%6,%7}, {%8,%9}, {%0,%1,%2,%3};"
        : "+f"(c[0]), "+f"(c[1]), "+f"(c[2]), "+f"(c[3])
        : "r"(a[0]), "r"(a[1]), "r"(a[2]), "r"(a[3]), "r"(b[0]), "r"(b[1]));
}

// ---------------- QKV projection: Y = X @ W^T + b (fp16 m16n8k16) ------------------
// CTA 128x128, BK=16, 256 thr = 8 warps, warp tile 64x32; double-buffered fp16 smem.
__global__ __launch_bounds__(256) void proj_kernel(
    const float* __restrict__ X, const float* __restrict__ W,
    const float* __restrict__ bias, int which)
{
    __shared__ __align__(16) unsigned Asw[2][128 * 12];
    __shared__ __align__(16) unsigned Bsw[2][128 * 12];
    float* out = (which == 0) ? g_qh : (which == 1) ? g_kh : g_vh;

    const int t = threadIdx.x;
    const int lane = t & 31, w = t >> 5;
    const int g = lane >> 2, tg = lane & 3;
    const int m0 = blockIdx.x * 128;
    const int n0 = blockIdx.y * 128;
    const int wm = (w & 1) * 64;
    const int wn = (w >> 1) * 32;

    float acc[4][4][4];
#pragma unroll
    for (int mt = 0; mt < 4; mt++)
#pragma unroll
        for (int nt = 0; nt < 4; nt++)
#pragma unroll
            for (int r = 0; r < 4; r++) acc[mt][nt][r] = 0.0f;

    int stage = 0;
    for (int k0 = 0; k0 < ND; k0 += 16, stage ^= 1) {
#pragma unroll
        for (int r = 0; r < 2; r++) {
            const int idx = t + 256 * r;
            const int row = idx >> 2, qc = (idx & 3) * 4;   // qc: 0,4,8,12 (halfs)
            float4 av = *(const float4*)(X + (size_t)(m0 + row) * ND + k0 + qc);
            *(uint2*)&Asw[stage][row * 12 + qc / 2] =
                make_uint2(packh2(av.x, av.y), packh2(av.z, av.w));
            float4 bv = *(const float4*)(W + (size_t)(n0 + row) * ND + k0 + qc);
            *(uint2*)&Bsw[stage][row * 12 + qc / 2] =
                make_uint2(packh2(bv.x, bv.y), packh2(bv.z, bv.w));
        }
        __syncthreads();   // single barrier/iter (skewed double buffer)
        unsigned a[4][4], b[4][2];
#pragma unroll
        for (int mt = 0; mt < 4; mt++) {
            const int m = wm + mt * 16 + g;
            a[mt][0] = Asw[stage][m * 12 + tg];
            a[mt][1] = Asw[stage][(m + 8) * 12 + tg];
            a[mt][2] = Asw[stage][m * 12 + tg + 4];
            a[mt][3] = Asw[stage][(m + 8) * 12 + tg + 4];
        }
#pragma unroll
        for (int nt = 0; nt < 4; nt++) {
            const int n = wn + nt * 8 + g;
            b[nt][0] = Bsw[stage][n * 12 + tg];
            b[nt][1] = Bsw[stage][n * 12 + tg + 4];
        }
#pragma unroll
        for (int mt = 0; mt < 4; mt++)
#pragma unroll
            for (int nt = 0; nt < 4; nt++)
                mma_f16(acc[mt][nt], a[mt], b[nt]);
    }

#pragma unroll
    for (int mt = 0; mt < 4; mt++) {
#pragma unroll
        for (int rr = 0; rr < 2; rr++) {
            const int row = m0 + wm + mt * 16 + g + rr * 8;
            const int b_ = row / NS, s = row % NS;
#pragma unroll
            for (int nt = 0; nt < 4; nt++) {
                const int col = n0 + wn + nt * 8 + tg * 2;
                const int h = col >> 6, d = col & 63;
                float2 val;
                val.x = acc[mt][nt][rr * 2 + 0] + bias[col];
                val.y = acc[mt][nt][rr * 2 + 1] + bias[col + 1];
                *(float2*)&out[(((size_t)b_ * NH + h) * NS + s) * HD + d] = val;
            }
        }
    }
}

// ---------------- attention: one block (512 thr, 16 warps) per (b,h,16-query tile) --
// smem: scores fp32[16][2052] | buf0[128][68] | buf1[128][68] | wmax[16][16] | inv_s[16]
// part[16][16][68]-style partials alias buf0 (used only after post-loop barrier)
__global__ __launch_bounds__(512) void attn_kernel(const int* __restrict__ mask,
                                                   float* __restrict__ attn_out)
{
    extern __shared__ __align__(16) float sm[];
    float* scores = sm;                        // 16*2052 = 32832 floats
    float* buf0   = sm + 16 * SROW;            // 128*68  = 8704
    float* buf1   = buf0 + 128 * 68;           // 128*68  = 8704
    float* wmax   = buf1 + 128 * 68;           // 256  (wmax[row][warp], transposed)
    float* inv_s  = wmax + 256;                // 16
    float* part   = buf0;                      // alias (phase-4 partials)

    const int t    = threadIdx.x;
    const int lane = t & 31, w = t >> 5;       // w: 0..15
    const int g = lane >> 2, tg = lane & 3;
    const int bid = blockIdx.x;
    const int qt = bid & 127;
    const int h  = (bid >> 7) & 15;
    const int b  = bid >> 11;
    const int q0 = qt * 16;

    const size_t bh = (size_t)(b * NH + h);
    const float* qbase = g_qh + bh * NS * HD;
    const float* kbase = g_kh + bh * NS * HD;
    const float* vbase = g_vh + bh * NS * HD;

    // ---- stage Q (scaled, tf32) into buf0 as Qs[16][68], preload fragments ----
    if (t < 256) {
        const int row = t >> 4, kd = (t & 15) * 4;
        float4 qv = *(const float4*)(qbase + (size_t)(q0 + row) * HD + kd);
        float4 sv;
        sv.x = f2tff(qv.x * SCALE); sv.y = f2tff(qv.y * SCALE);
        sv.z = f2tff(qv.z * SCALE); sv.w = f2tff(qv.w * SCALE);
        *(float4*)(buf0 + row * 68 + kd) = sv;
    }
    __syncthreads();
    unsigned aq[8][4];
#pragma unroll
    for (int kk = 0; kk < 8; kk++) {
        aq[kk][0] = __float_as_uint(buf0[g * 68 + kk * 8 + tg]);
        aq[kk][1] = __float_as_uint(buf0[(g + 8) * 68 + kk * 8 + tg]);
        aq[kk][2] = __float_as_uint(buf0[g * 68 + kk * 8 + 4 + tg]);
        aq[kk][3] = __float_as_uint(buf0[(g + 8) * 68 + kk * 8 + 4 + tg]);
    }
    __syncthreads();

    // ---- phase 1: scores = masked (q*scale) @ K^T, 128-key chunks, double-buffered.
    //      Masks fused into epilogue; per-row running max tracked in registers. ----
    const int qr0 = q0 + g, qr1 = q0 + g + 8;
    const int* mrow0 = mask + ((size_t)b * NS + qr0) * NS;
    const int* mrow1 = mask + ((size_t)b * NS + qr1) * NS;
    float mx0 = -3.0e38f, mx1 = -3.0e38f;

    for (int jc = 0; jc < 16; jc++) {
        const int j0 = jc * 128;
        float* bufc = (jc & 1) ? buf1 : buf0;
#pragma unroll
        for (int r = 0; r < 4; r++) {
            const int idx = t + 512 * r;
            const int key = idx >> 4, kd = (idx & 15) * 4;
            float4 kv = *(const float4*)(kbase + (size_t)(j0 + key) * HD + kd);
            float4 s4;
            s4.x = f2tff(kv.x); s4.y = f2tff(kv.y);
            s4.z = f2tff(kv.z); s4.w = f2tff(kv.w);
            *(float4*)(bufc + key * 68 + kd) = s4;
        }
        __syncthreads();
        float c0[4] = {0.f, 0.f, 0.f, 0.f}, c1[4] = {0.f, 0.f, 0.f, 0.f};
#pragma unroll
        for (int kp = 0; kp < 4; kp++) {
            unsigned b0[2], b1[2];
            b0[0] = __float_as_uint(bufc[(w * 8 + g) * 68 + (2 * kp) * 8 + tg]);
            b0[1] = __float_as_uint(bufc[(w * 8 + g) * 68 + (2 * kp) * 8 + 4 + tg]);
            b1[0] = __float_as_uint(bufc[(w * 8 + g) * 68 + (2 * kp + 1) * 8 + tg]);
            b1[1] = __float_as_uint(bufc[(w * 8 + g) * 68 + (2 * kp + 1) * 8 + 4 + tg]);
            mma_tf32(c0, aq[2 * kp], b0);
            mma_tf32(c1, aq[2 * kp + 1], b1);
        }
        const int col = j0 + w * 8 + tg * 2;
        float s00 = c0[0] + c1[0], s01 = c0[1] + c1[1];
        float s10 = c0[2] + c1[2], s11 = c0[3] + c1[3];
        int2 mv0 = *(const int2*)(mrow0 + col);
        int2 mv1 = *(const int2*)(mrow1 + col);
        s00 += (1.0f - (float)mv0.x) * NEGV + ((col     > qr0) ? NEGV : 0.0f);
        s01 += (1.0f - (float)mv0.y) * NEGV + ((col + 1 > qr0) ? NEGV : 0.0f);
        s10 += (1.0f - (float)mv1.x) * NEGV + ((col     > qr1) ? NEGV : 0.0f);
        s11 += (1.0f - (float)mv1.y) * NEGV + ((col + 1 > qr1) ? NEGV : 0.0f);
        *(float2*)&scores[g * SROW + col]       = make_float2(s00, s01);
        *(float2*)&scores[(g + 8) * SROW + col] = make_float2(s10, s11);
        mx0 = fmaxf(mx0, fmaxf(s00, s01));
        mx1 = fmaxf(mx1, fmaxf(s10, s11));
    }
    // reduce row maxes across the 4 tg lanes, then publish per-warp partials
    mx0 = fmaxf(mx0, __shfl_xor_sync(0xffffffffu, mx0, 1));
    mx0 = fmaxf(mx0, __shfl_xor_sync(0xffffffffu, mx0, 2));
    mx1 = fmaxf(mx1, __shfl_xor_sync(0xffffffffu, mx1, 1));
    mx1 = fmaxf(mx1, __shfl_xor_sync(0xffffffffu, mx1, 2));
    if (tg == 0) {
        wmax[g * 16 + w]       = mx0;   // wmax[row][warp]
        wmax[(g + 8) * 16 + w] = mx1;
    }
    __syncthreads();

    // ---- phase 2: single-pass softmax; warp w owns row w (scores already masked) ----
    {
        const int i = w;
        float mx = wmax[i * 16 + (lane & 15)];
#pragma unroll
        for (int o = 8; o > 0; o >>= 1) mx = fmaxf(mx, __shfl_xor_sync(0xffffffffu, mx, o));
        float sum = 0.0f;
        for (int k4 = lane * 4; k4 < NS; k4 += 128) {
            float4 s4 = *(float4*)(scores + i * SROW + k4);
            s4.x = __expf(s4.x - mx); s4.y = __expf(s4.y - mx);
            s4.z = __expf(s4.z - mx); s4.w = __expf(s4.w - mx);
            *(float4*)(scores + i * SROW + k4) = s4;
            sum += (s4.x + s4.y) + (s4.z + s4.w);
        }
#pragma unroll
        for (int o = 16; o > 0; o >>= 1) sum += __shfl_xor_sync(0xffffffffu, sum, o);
        if (lane == 0) inv_s[i] = 1.0f / sum;
    }
    __syncthreads();

    // ---- phase 3: write normalized attention probabilities (float4) ----
    if (attn_out) {
        for (int idx = t; idx < 16 * 512; idx += 512) {
            const int i = idx >> 9, j = (idx & 511) * 4;
            float4 p = *(float4*)(scores + i * SROW + j);
            const float iv = inv_s[i];
            p.x *= iv; p.y *= iv; p.z *= iv; p.w *= iv;
            *(float4*)&attn_out[(bh * NS + q0 + i) * (size_t)NS + j] = p;
        }
    }

    // ---- phase 4: out = P @ V (tf32); warp w -> 8 keys, full 64-wide N ----
    {
        float pc[8][4];
#pragma unroll
        for (int nt = 0; nt < 8; nt++)
#pragma unroll
            for (int r = 0; r < 4; r++) pc[nt][r] = 0.0f;

        for (int jc = 0; jc < 16; jc++) {
            const int j0 = jc * 128;
            float* bufc = (jc & 1) ? buf1 : buf0;
#pragma unroll
            for (int r = 0; r < 4; r++) {
                const int idx = t + 512 * r;
                const int key = idx >> 4, kd = (idx & 15) * 4;
                float4 vv = *(const float4*)(vbase + (size_t)(j0 + key) * HD + kd);
                float4 s4;
                s4.x = f2tff(vv.x); s4.y = f2tff(vv.y);
                s4.z = f2tff(vv.z); s4.w = f2tff(vv.w);
                *(float4*)(bufc + key * 68 + kd) = s4;
            }
            __syncthreads();
            const int kr = j0 + w * 8;     // global key base
            const int lk = w * 8;          // local in bufc
            unsigned a[4];
            a[0] = f2tf(scores[g * SROW + kr + tg]);
            a[1] = f2tf(scores[(g + 8) * SROW + kr + tg]);
            a[2] = f2tf(scores[g * SROW + kr + 4 + tg]);
            a[3] = f2tf(scores[(g + 8) * SROW + kr + 4 + tg]);
#pragma unroll
            for (int nt = 0; nt < 8; nt++) {
                unsigned bb[2];
                bb[0] = __float_as_uint(bufc[(lk + tg) * 68 + nt * 8 + g]);
                bb[1] = __float_as_uint(bufc[(lk + 4 + tg) * 68 + nt * 8 + g]);
                mma_tf32(pc[nt], a, bb);
            }
        }
        __syncthreads();   // all MMA reads done before partials alias the V buffers

#pragma unroll
        for (int nt = 0; nt < 8; nt++) {
            const int col = nt * 8 + tg * 2;
            *(float2*)&part[w * 1088 + g * 68 + col]       = make_float2(pc[nt][0], pc[nt][1]);
            *(float2*)&part[w * 1088 + (g + 8) * 68 + col] = make_float2(pc[nt][2], pc[nt][3]);
        }
        __syncthreads();
        for (int idx = t; idx < 1024; idx += 512) {
            const int i = idx >> 6, dd = idx & 63;
            float s = 0.0f;
#pragma unroll
            for (int ww = 0; ww < 16; ww++) s += part[ww * 1088 + i * 68 + dd];
            g_ao[((size_t)b * NS + q0 + i) * ND + h * HD + dd] = s * inv_s[i];
        }
    }
}

// ---------------- residual + LayerNorm, one block per (b,s) row --------------------
__global__ __launch_bounds__(256) void ln_kernel(const float* __restrict__ resid,
                                                 const float* __restrict__ gam,
                                                 const float* __restrict__ bet,
                                                 float* __restrict__ out)
{
    __shared__ float xb[ND];
    __shared__ float red[8];
    const int r = blockIdx.x;
    const int t = threadIdx.x;
    const int lane = t & 31, w = t >> 5;
    const size_t base = (size_t)r * ND;

    float lsum = 0.0f;
    for (int j = t; j < ND; j += 256) {
        const float x = g_ao[base + j] + resid[base + j];
        xb[j] = x;
        lsum += x;
    }
#pragma unroll
    for (int o = 16; o > 0; o >>= 1) lsum += __shfl_xor_sync(0xffffffffu, lsum, o);
    if (lane == 0) red[w] = lsum;
    __syncthreads();
    float tot = 0.0f;
#pragma unroll
    for (int w2 = 0; w2 < 8; w2++) tot += red[w2];
    const float mu = tot * (1.0f / ND);
    __syncthreads();

    float lv = 0.0f;
    for (int j = t; j < ND; j += 256) {
        const float dd = xb[j] - mu;
        lv += dd * dd;
    }
#pragma unroll
    for (int o = 16; o > 0; o >>= 1) lv += __shfl_xor_sync(0xffffffffu, lv, o);
    if (lane == 0) red[w] = lv;
    __syncthreads();
    float vtot = 0.0f;
#pragma unroll
    for (int w2 = 0; w2 < 8; w2++) vtot += red[w2];
    const float rstd = rsqrtf(vtot * (1.0f / ND) + 1e-5f);

    for (int j = t; j < ND; j += 256)
        out[base + j] = (xb[j] - mu) * rstd * gam[j] + bet[j];
}

// ---------------- launch -----------------------------------------------------------
extern "C" void kernel_launch(void* const* d_in, const int* in_sizes, int n_in,
                              void* d_out, int out_size)
{
    const float* q    = (const float*)d_in[0];
    const float* k    = (const float*)d_in[1];
    const float* v    = (const float*)d_in[2];
    const int*   mask = (const int*)  d_in[3];
    const float* Wq   = (const float*)d_in[4];
    const float* bq   = (const float*)d_in[5];
    const float* Wk   = (const float*)d_in[6];
    const float* bk   = (const float*)d_in[7];
    const float* Wv   = (const float*)d_in[8];
    const float* bv   = (const float*)d_in[9];
    const float* ln_g = (const float*)d_in[10];
    const float* ln_b = (const float*)d_in[11];
    float* out = (float*)d_out;

    // scores + 2 staging bufs + wmax + inv_s
    const int smem_bytes = (16 * SROW + 2 * 128 * 68 + 256 + 16) * (int)sizeof(float); // 202,112 B
    cudaFuncSetAttribute(attn_kernel, cudaFuncAttributeMaxDynamicSharedMemorySize, smem_bytes);

    dim3 pg(64, 8);
    proj_kernel<<<pg, 256>>>(q, Wq, bq, 0);
    proj_kernel<<<pg, 256>>>(k, Wk, bk, 1);
    proj_kernel<<<pg, 256>>>(v, Wv, bv, 2);

    float* attn = nullptr;
    const long long need = (long long)NB * NS * ND + (long long)NB * NH * NS * NS;
    if ((long long)out_size >= need) attn = out + (size_t)NB * NS * ND;

    attn_kernel<<<NB * NH * (NS / 16), 512, smem_bytes>>>(mask, attn);
    ln_kernel<<<NB * NS, 256>>>(q, ln_g, ln_b, out);
}

// round 13
// speedup vs baseline: 1.7171x; 1.7171x over previous
#include <cuda_runtime.h>
#include <cuda_fp16.h>

#define NB 4
#define NS 2048
#define ND 1024
#define NH 16
#define HD 64
#define NEGV (-10000.0f)
#define SCALE 0.125f
#define SROW 2052   // fp32 score row stride; %32==4 conflict-free, %4==0 for float4

// ---------------- scratch (static device arrays; no runtime allocation) ------------
__device__ float g_qh[NB * NH * NS * HD];
__device__ float g_kh[NB * NH * NS * HD];
__device__ float g_vh[NB * NH * NS * HD];
__device__ float g_ao[NB * NS * ND];

// ---------------- helpers ----------------------------------------------------------
__device__ __forceinline__ unsigned f2tf(float x) {
    unsigned u; asm("cvt.rna.tf32.f32 %0, %1;" : "=r"(u) : "f"(x)); return u;
}
__device__ __forceinline__ float f2tff(float x) { return __uint_as_float(f2tf(x)); }

__device__ __forceinline__ unsigned packh2(float x, float y) {
    __half2 h = __floats2half2_rn(x, y);
    return *reinterpret_cast<unsigned*>(&h);
}

__device__ __forceinline__ void cp16(float* dst, const float* src) {
    unsigned d = (unsigned)__cvta_generic_to_shared(dst);
    asm volatile("cp.async.cg.shared.global [%0], [%1], 16;" :: "r"(d), "l"(src));
}
__device__ __forceinline__ void cp_commit() { asm volatile("cp.async.commit_group;" ::: "memory"); }
__device__ __forceinline__ void cp_wait1()  { asm volatile("cp.async.wait_group 1;" ::: "memory"); }
__device__ __forceinline__ void cp_wait0()  { asm volatile("cp.async.wait_group 0;" ::: "memory"); }

__device__ __forceinline__ void mma_tf32(float c[4], const unsigned a[4], const unsigned b[2]) {
    asm volatile(
        "mma.sync.aligned.m16n8k8.row.col.f32.tf32.tf32.f32 "
        "{%0,%1,%2,%3}, {%4,%5,%6,%7}, {%8,%9}, {%0,%1,%2,%3};"
        : "+f"(c[0]), "+f"(c[1]), "+f"(c[2]), "+f"(c[3])
        : "r"(a[0]), "r"(a[1]), "r"(a[2]), "r"(a[3]), "r"(b[0]), "r"(b[1]));
}

__device__ __forceinline__ void mma_f16(float c[4], const unsigned a[4], const unsigned b[2]) {
    asm volatile(
        "mma.sync.aligned.m16n8k16.row.col.f32.f16.f16.f32 "
        "{%0,%1,%2,%3}, {%4,%5,%6,%7}, {%8,%9}, {%0,%1,%2,%3};"
        : "+f"(c[0]), "+f"(c[1]), "+f"(c[2]), "+f"(c[3])
        : "r"(a[0]), "r"(a[1]), "r"(a[2]), "r"(a[3]), "r"(b[0]), "r"(b[1]));
}

// ---------------- QKV projection: Y = X @ W^T + b (fp16 m16n8k16) ------------------
// CTA 128x128, BK=16, 256 thr = 8 warps, warp tile 64x32; double-buffered fp16 smem.
__global__ __launch_bounds__(256) void proj_kernel(
    const float* __restrict__ X, const float* __restrict__ W,
    const float* __restrict__ bias, int which)
{
    __shared__ __align__(16) unsigned Asw[2][128 * 12];
    __shared__ __align__(16) unsigned Bsw[2][128 * 12];
    float* out = (which == 0) ? g_qh : (which == 1) ? g_kh : g_vh;

    const int t = threadIdx.x;
    const int lane = t & 31, w = t >> 5;
    const int g = lane >> 2, tg = lane & 3;
    const int m0 = blockIdx.x * 128;
    const int n0 = blockIdx.y * 128;
    const int wm = (w & 1) * 64;
    const int wn = (w >> 1) * 32;

    float acc[4][4][4];
#pragma unroll
    for (int mt = 0; mt < 4; mt++)
#pragma unroll
        for (int nt = 0; nt < 4; nt++)
#pragma unroll
            for (int r = 0; r < 4; r++) acc[mt][nt][r] = 0.0f;

    int stage = 0;
    for (int k0 = 0; k0 < ND; k0 += 16, stage ^= 1) {
#pragma unroll
        for (int r = 0; r < 2; r++) {
            const int idx = t + 256 * r;
            const int row = idx >> 2, qc = (idx & 3) * 4;   // qc: 0,4,8,12 (halfs)
            float4 av = *(const float4*)(X + (size_t)(m0 + row) * ND + k0 + qc);
            *(uint2*)&Asw[stage][row * 12 + qc / 2] =
                make_uint2(packh2(av.x, av.y), packh2(av.z, av.w));
            float4 bv = *(const float4*)(W + (size_t)(n0 + row) * ND + k0 + qc);
            *(uint2*)&Bsw[stage][row * 12 + qc / 2] =
                make_uint2(packh2(bv.x, bv.y), packh2(bv.z, bv.w));
        }
        __syncthreads();   // single barrier/iter (skewed double buffer)
        unsigned a[4][4], b[4][2];
#pragma unroll
        for (int mt = 0; mt < 4; mt++) {
            const int m = wm + mt * 16 + g;
            a[mt][0] = Asw[stage][m * 12 + tg];
            a[mt][1] = Asw[stage][(m + 8) * 12 + tg];
            a[mt][2] = Asw[stage][m * 12 + tg + 4];
            a[mt][3] = Asw[stage][(m + 8) * 12 + tg + 4];
        }
#pragma unroll
        for (int nt = 0; nt < 4; nt++) {
            const int n = wn + nt * 8 + g;
            b[nt][0] = Bsw[stage][n * 12 + tg];
            b[nt][1] = Bsw[stage][n * 12 + tg + 4];
        }
#pragma unroll
        for (int mt = 0; mt < 4; mt++)
#pragma unroll
            for (int nt = 0; nt < 4; nt++)
                mma_f16(acc[mt][nt], a[mt], b[nt]);
    }

#pragma unroll
    for (int mt = 0; mt < 4; mt++) {
#pragma unroll
        for (int rr = 0; rr < 2; rr++) {
            const int row = m0 + wm + mt * 16 + g + rr * 8;
            const int b_ = row / NS, s = row % NS;
#pragma unroll
            for (int nt = 0; nt < 4; nt++) {
                const int col = n0 + wn + nt * 8 + tg * 2;
                const int h = col >> 6, d = col & 63;
                float2 val;
                val.x = acc[mt][nt][rr * 2 + 0] + bias[col];
                val.y = acc[mt][nt][rr * 2 + 1] + bias[col + 1];
                *(float2*)&out[(((size_t)b_ * NH + h) * NS + s) * HD + d] = val;
            }
        }
    }
}

// ---------------- attention: one block (512 thr, 16 warps) per (b,h,16-query tile) --
// smem: scores fp32[16][2052] | buf0[128][68] | buf1[128][68] | inv_s[16]
// K/V staged raw fp32 via cp.async; tf32/consumer-side cvt (bit-identical numerics).
// part[8][16][68] aliases buf0 (used only after post-loop barrier in phase 4).
__global__ __launch_bounds__(512) void attn_kernel(const int* __restrict__ mask,
                                                   float* __restrict__ attn_out)
{
    extern __shared__ __align__(16) float sm[];
    float* scores = sm;                        // 16*2052 = 32832 floats
    float* buf0   = sm + 16 * SROW;            // 128*68  = 8704
    float* buf1   = buf0 + 128 * 68;           // 128*68  = 8704
    float* inv_s  = buf1 + 128 * 68;           // 16
    float* part   = buf0;                      // alias (phase-4 partials)

    const int t    = threadIdx.x;
    const int lane = t & 31, w = t >> 5;       // w: 0..15
    const int g = lane >> 2, tg = lane & 3;
    const int bid = blockIdx.x;
    const int qt = bid & 127;
    const int h  = (bid >> 7) & 15;
    const int b  = bid >> 11;
    const int q0 = qt * 16;

    const size_t bh = (size_t)(b * NH + h);
    const float* qbase = g_qh + bh * NS * HD;
    const float* kbase = g_kh + bh * NS * HD;
    const float* vbase = g_vh + bh * NS * HD;

    // per-thread staging coordinates (4 x 16B cp.async per 128-row chunk)
    const int skey = t >> 4;            // 0..31 (+32 per r)
    const int skd4 = (t & 15);          // 16B unit within a 64-float row

    // ---- stage Q (scaled, tf32) into buf0 as Qs[16][68], preload fragments ----
    if (t < 256) {
        const int row = t >> 4, kd = (t & 15) * 4;
        float4 qv = *(const float4*)(qbase + (size_t)(q0 + row) * HD + kd);
        float4 sv;
        sv.x = f2tff(qv.x * SCALE); sv.y = f2tff(qv.y * SCALE);
        sv.z = f2tff(qv.z * SCALE); sv.w = f2tff(qv.w * SCALE);
        *(float4*)(buf0 + row * 68 + kd) = sv;
    }
    __syncthreads();
    unsigned aq[8][4];
#pragma unroll
    for (int kk = 0; kk < 8; kk++) {
        aq[kk][0] = __float_as_uint(buf0[g * 68 + kk * 8 + tg]);
        aq[kk][1] = __float_as_uint(buf0[(g + 8) * 68 + kk * 8 + tg]);
        aq[kk][2] = __float_as_uint(buf0[g * 68 + kk * 8 + 4 + tg]);
        aq[kk][3] = __float_as_uint(buf0[(g + 8) * 68 + kk * 8 + 4 + tg]);
    }
    __syncthreads();

    // ---- phase 1: scores = (q*scale) @ K^T; cp.async skewed 2-buffer pipeline ----
    {
#pragma unroll
        for (int r = 0; r < 4; r++)
            cp16(buf0 + (skey + 32 * r) * 68 + skd4 * 4,
                 kbase + (size_t)(skey + 32 * r) * HD + skd4 * 4);
        cp_commit();
    }
    for (int jc = 0; jc < 16; jc++) {
        float* bufc = (jc & 1) ? buf1 : buf0;
        if (jc < 15) {
            float* bufn = (jc & 1) ? buf0 : buf1;
            const float* src = kbase + (size_t)(jc + 1) * 128 * HD;
#pragma unroll
            for (int r = 0; r < 4; r++)
                cp16(bufn + (skey + 32 * r) * 68 + skd4 * 4,
                     src + (size_t)(skey + 32 * r) * HD + skd4 * 4);
            cp_commit();
            cp_wait1();
        } else {
            cp_wait0();
        }
        __syncthreads();
        float c0[4] = {0.f, 0.f, 0.f, 0.f}, c1[4] = {0.f, 0.f, 0.f, 0.f};
#pragma unroll
        for (int kp = 0; kp < 4; kp++) {
            unsigned b0[2], b1[2];
            b0[0] = f2tf(bufc[(w * 8 + g) * 68 + (2 * kp) * 8 + tg]);
            b0[1] = f2tf(bufc[(w * 8 + g) * 68 + (2 * kp) * 8 + 4 + tg]);
            b1[0] = f2tf(bufc[(w * 8 + g) * 68 + (2 * kp + 1) * 8 + tg]);
            b1[1] = f2tf(bufc[(w * 8 + g) * 68 + (2 * kp + 1) * 8 + 4 + tg]);
            mma_tf32(c0, aq[2 * kp], b0);
            mma_tf32(c1, aq[2 * kp + 1], b1);
        }
        const int col = jc * 128 + w * 8 + tg * 2;
        *(float2*)&scores[g * SROW + col]       = make_float2(c0[0] + c1[0], c0[1] + c1[1]);
        *(float2*)&scores[(g + 8) * SROW + col] = make_float2(c0[2] + c1[2], c0[3] + c1[3]);
        __syncthreads();
    }

    // ---- prefetch V chunk 0 now: its latency hides under softmax + attn write ----
    {
#pragma unroll
        for (int r = 0; r < 4; r++)
            cp16(buf0 + (skey + 32 * r) * 68 + skd4 * 4,
                 vbase + (size_t)(skey + 32 * r) * HD + skd4 * 4);
        cp_commit();
    }

    // ---- phase 2: masks + softmax; warp w owns row w; vectorized ----
    {
        const int i = w;
        const int qrow = q0 + i;
        const int* mrow = mask + ((size_t)b * NS + qrow) * NS;
        float mx = -3.0e38f;
        for (int k4 = lane * 4; k4 < NS; k4 += 128) {
            int4 m4 = *(const int4*)(mrow + k4);
            float4 s4 = *(float4*)(scores + i * SROW + k4);
            s4.x += (1.0f - (float)m4.x) * NEGV + ((k4 + 0 > qrow) ? NEGV : 0.0f);
            s4.y += (1.0f - (float)m4.y) * NEGV + ((k4 + 1 > qrow) ? NEGV : 0.0f);
            s4.z += (1.0f - (float)m4.z) * NEGV + ((k4 + 2 > qrow) ? NEGV : 0.0f);
            s4.w += (1.0f - (float)m4.w) * NEGV + ((k4 + 3 > qrow) ? NEGV : 0.0f);
            *(float4*)(scores + i * SROW + k4) = s4;
            mx = fmaxf(mx, fmaxf(fmaxf(s4.x, s4.y), fmaxf(s4.z, s4.w)));
        }
#pragma unroll
        for (int o = 16; o > 0; o >>= 1) mx = fmaxf(mx, __shfl_xor_sync(0xffffffffu, mx, o));
        float sum = 0.0f;
        for (int k4 = lane * 4; k4 < NS; k4 += 128) {
            float4 s4 = *(float4*)(scores + i * SROW + k4);
            s4.x = __expf(s4.x - mx); s4.y = __expf(s4.y - mx);
            s4.z = __expf(s4.z - mx); s4.w = __expf(s4.w - mx);
            *(float4*)(scores + i * SROW + k4) = s4;
            sum += (s4.x + s4.y) + (s4.z + s4.w);
        }
#pragma unroll
        for (int o = 16; o > 0; o >>= 1) sum += __shfl_xor_sync(0xffffffffu, sum, o);
        if (lane == 0) inv_s[i] = 1.0f / sum;
    }
    __syncthreads();

    // ---- phase 3: write normalized attention probabilities (float4) ----
    if (attn_out) {
        for (int idx = t; idx < 16 * 512; idx += 512) {
            const int i = idx >> 9, j = (idx & 511) * 4;
            float4 p = *(float4*)(scores + i * SROW + j);
            const float iv = inv_s[i];
            p.x *= iv; p.y *= iv; p.z *= iv; p.w *= iv;
            *(float4*)&attn_out[(bh * NS + q0 + i) * (size_t)NS + j] = p;
        }
    }

    // ---- phase 4: out = P @ V (tf32); warp w -> key-group (w>>1), d-half (w&1)*32 ----
    {
        const int kg = w >> 1, dh = (w & 1) * 32;
        float pc[4][4];
#pragma unroll
        for (int nt = 0; nt < 4; nt++)
#pragma unroll
            for (int r = 0; r < 4; r++) pc[nt][r] = 0.0f;

        for (int jc = 0; jc < 16; jc++) {
            const int j0 = jc * 128;
            float* bufc = (jc & 1) ? buf1 : buf0;
            if (jc < 15) {
                float* bufn = (jc & 1) ? buf0 : buf1;
                const float* src = vbase + (size_t)(jc + 1) * 128 * HD;
#pragma unroll
                for (int r = 0; r < 4; r++)
                    cp16(bufn + (skey + 32 * r) * 68 + skd4 * 4,
                         src + (size_t)(skey + 32 * r) * HD + skd4 * 4);
                cp_commit();
                cp_wait1();
            } else {
                cp_wait0();
            }
            __syncthreads();
#pragma unroll
            for (int s = 0; s < 2; s++) {
                const int kr = j0 + kg * 16 + s * 8;      // global key base
                const int lk = kg * 16 + s * 8;           // local in bufc
                unsigned a[4];
                a[0] = f2tf(scores[g * SROW + kr + tg]);
                a[1] = f2tf(scores[(g + 8) * SROW + kr + tg]);
                a[2] = f2tf(scores[g * SROW + kr + 4 + tg]);
                a[3] = f2tf(scores[(g + 8) * SROW + kr + 4 + tg]);
#pragma unroll
                for (int nt = 0; nt < 4; nt++) {
                    unsigned bb[2];
                    bb[0] = f2tf(bufc[(lk + tg) * 68 + dh + nt * 8 + g]);
                    bb[1] = f2tf(bufc[(lk + 4 + tg) * 68 + dh + nt * 8 + g]);
                    mma_tf32(pc[nt], a, bb);
                }
            }
            __syncthreads();
        }
        // after final barrier: all MMA reads done; partials may alias buf0

#pragma unroll
        for (int nt = 0; nt < 4; nt++) {
            const int col = dh + nt * 8 + tg * 2;
            *(float2*)&part[kg * 1088 + g * 68 + col]       = make_float2(pc[nt][0], pc[nt][1]);
            *(float2*)&part[kg * 1088 + (g + 8) * 68 + col] = make_float2(pc[nt][2], pc[nt][3]);
        }
        __syncthreads();
        for (int idx = t; idx < 1024; idx += 512) {
            const int i = idx >> 6, dd = idx & 63;
            float s = 0.0f;
#pragma unroll
            for (int ww = 0; ww < 8; ww++) s += part[ww * 1088 + i * 68 + dd];
            g_ao[((size_t)b * NS + q0 + i) * ND + h * HD + dd] = s * inv_s[i];
        }
    }
}

// ---------------- residual + LayerNorm, one block per (b,s) row --------------------
__global__ __launch_bounds__(256) void ln_kernel(const float* __restrict__ resid,
                                                 const float* __restrict__ gam,
                                                 const float* __restrict__ bet,
                                                 float* __restrict__ out)
{
    __shared__ float xb[ND];
    __shared__ float red[8];
    const int r = blockIdx.x;
    const int t = threadIdx.x;
    const int lane = t & 31, w = t >> 5;
    const size_t base = (size_t)r * ND;

    float lsum = 0.0f;
    for (int j = t; j < ND; j += 256) {
        const float x = g_ao[base + j] + resid[base + j];
        xb[j] = x;
        lsum += x;
    }
#pragma unroll
    for (int o = 16; o > 0; o >>= 1) lsum += __shfl_xor_sync(0xffffffffu, lsum, o);
    if (lane == 0) red[w] = lsum;
    __syncthreads();
    float tot = 0.0f;
#pragma unroll
    for (int w2 = 0; w2 < 8; w2++) tot += red[w2];
    const float mu = tot * (1.0f / ND);
    __syncthreads();

    float lv = 0.0f;
    for (int j = t; j < ND; j += 256) {
        const float dd = xb[j] - mu;
        lv += dd * dd;
    }
#pragma unroll
    for (int o = 16; o > 0; o >>= 1) lv += __shfl_xor_sync(0xffffffffu, lv, o);
    if (lane == 0) red[w] = lv;
    __syncthreads();
    float vtot = 0.0f;
#pragma unroll
    for (int w2 = 0; w2 < 8; w2++) vtot += red[w2];
    const float rstd = rsqrtf(vtot * (1.0f / ND) + 1e-5f);

    for (int j = t; j < ND; j += 256)
        out[base + j] = (xb[j] - mu) * rstd * gam[j] + bet[j];
}

// ---------------- launch -----------------------------------------------------------
extern "C" void kernel_launch(void* const* d_in, const int* in_sizes, int n_in,
                              void* d_out, int out_size)
{
    const float* q    = (const float*)d_in[0];
    const float* k    = (const float*)d_in[1];
    const float* v    = (const float*)d_in[2];
    const int*   mask = (const int*)  d_in[3];
    const float* Wq   = (const float*)d_in[4];
    const float* bq   = (const float*)d_in[5];
    const float* Wk   = (const float*)d_in[6];
    const float* bk   = (const float*)d_in[7];
    const float* Wv   = (const float*)d_in[8];
    const float* bv   = (const float*)d_in[9];
    const float* ln_g = (const float*)d_in[10];
    const float* ln_b = (const float*)d_in[11];
    float* out = (float*)d_out;

    const int smem_bytes = (16 * SROW + 2 * 128 * 68 + 16) * (int)sizeof(float); // 201,024 B
    cudaFuncSetAttribute(attn_kernel, cudaFuncAttributeMaxDynamicSharedMemorySize, smem_bytes);

    dim3 pg(64, 8);
    proj_kernel<<<pg, 256>>>(q, Wq, bq, 0);
    proj_kernel<<<pg, 256>>>(k, Wk, bk, 1);
    proj_kernel<<<pg, 256>>>(v, Wv, bv, 2);

    float* attn = nullptr;
    const long long need = (long long)NB * NS * ND + (long long)NB * NH * NS * NS;
    if ((long long)out_size >= need) attn = out + (size_t)NB * NS * ND;

    attn_kernel<<<NB * NH * (NS / 16), 512, smem_bytes>>>(mask, attn);
    ln_kernel<<<NB * NS, 256>>>(q, ln_g, ln_b, out);
}

// round 15
// speedup vs baseline: 2.1493x; 1.2517x over previous
#include <cuda_runtime.h>
#include <cuda_fp16.h>

#define NB 4
#define NS 2048
#define ND 1024
#define NH 16
#define HD 64
#define NEGV (-10000.0f)
#define SCALE 0.125f

// ---------------- scratch (static device arrays; no runtime allocation) ------------
__device__ __half g_qh2[NB * NH * NS * HD];   // [bh][s][d] fp16
__device__ __half g_kh2[NB * NH * NS * HD];   // [bh][s][d] fp16
__device__ __half g_vh2[NB * NH * HD * NS];   // [bh][d][s] fp16 (transposed)
__device__ float  g_ao [NB * NS * ND];        // attention output pre-LN
__device__ float  g_sc_fb[NB * NH * NS * NS]; // score scratch if attn output absent

// ---------------- helpers ----------------------------------------------------------
__device__ __forceinline__ unsigned packh2(float x, float y) {
    __half2 h = __floats2half2_rn(x, y);
    return *reinterpret_cast<unsigned*>(&h);
}
__device__ __forceinline__ void cp16g(void* dst_smem, const void* src) {
    unsigned d = (unsigned)__cvta_generic_to_shared(dst_smem);
    asm volatile("cp.async.cg.shared.global [%0], [%1], 16;" :: "r"(d), "l"(src));
}
__device__ __forceinline__ void cp_commit()  { asm volatile("cp.async.commit_group;" ::: "memory"); }
__device__ __forceinline__ void cp_wait0()   { asm volatile("cp.async.wait_group 0;" ::: "memory"); }

__device__ __forceinline__ void mma_f16(float c[4], const unsigned a[4], const unsigned b[2]) {
    asm volatile(
        "mma.sync.aligned.m16n8k16.row.col.f32.f16.f16.f32 "
        "{%0,%1,%2,%3}, {%4,%5,%6,%7}, {%8,%9}, {%0,%1,%2,%3};"
        : "+f"(c[0]), "+f"(c[1]), "+f"(c[2]), "+f"(c[3])
        : "r"(a[0]), "r"(a[1]), "r"(a[2]), "r"(a[3]), "r"(b[0]), "r"(b[1]));
}

// ---------------- QKV projection: Y = X @ W^T + b (fp16 m16n8k16) ------------------
// CTA 128x128, BK=16, 256 thr = 8 warps, warp tile 64x32; double-buffered fp16 smem.
// which 0/1 -> fp16 [bh][s][d]; which 2 -> fp16 transposed [bh][d][s].
__global__ __launch_bounds__(256) void proj_kernel(
    const float* __restrict__ X, const float* __restrict__ W,
    const float* __restrict__ bias, int which)
{
    __shared__ __align__(16) unsigned Asw[2][128 * 12];
    __shared__ __align__(16) unsigned Bsw[2][128 * 12];

    const int t = threadIdx.x;
    const int lane = t & 31, w = t >> 5;
    const int g = lane >> 2, tg = lane & 3;
    const int m0 = blockIdx.x * 128;
    const int n0 = blockIdx.y * 128;
    const int wm = (w & 1) * 64;
    const int wn = (w >> 1) * 32;

    float acc[4][4][4];
#pragma unroll
    for (int mt = 0; mt < 4; mt++)
#pragma unroll
        for (int nt = 0; nt < 4; nt++)
#pragma unroll
            for (int r = 0; r < 4; r++) acc[mt][nt][r] = 0.0f;

    int stage = 0;
    for (int k0 = 0; k0 < ND; k0 += 16, stage ^= 1) {
#pragma unroll
        for (int r = 0; r < 2; r++) {
            const int idx = t + 256 * r;
            const int row = idx >> 2, qc = (idx & 3) * 4;
            float4 av = *(const float4*)(X + (size_t)(m0 + row) * ND + k0 + qc);
            *(uint2*)&Asw[stage][row * 12 + qc / 2] =
                make_uint2(packh2(av.x, av.y), packh2(av.z, av.w));
            float4 bv = *(const float4*)(W + (size_t)(n0 + row) * ND + k0 + qc);
            *(uint2*)&Bsw[stage][row * 12 + qc / 2] =
                make_uint2(packh2(bv.x, bv.y), packh2(bv.z, bv.w));
        }
        __syncthreads();   // single barrier/iter (skewed double buffer)
        unsigned a[4][4], b[4][2];
#pragma unroll
        for (int mt = 0; mt < 4; mt++) {
            const int m = wm + mt * 16 + g;
            a[mt][0] = Asw[stage][m * 12 + tg];
            a[mt][1] = Asw[stage][(m + 8) * 12 + tg];
            a[mt][2] = Asw[stage][m * 12 + tg + 4];
            a[mt][3] = Asw[stage][(m + 8) * 12 + tg + 4];
        }
#pragma unroll
        for (int nt = 0; nt < 4; nt++) {
            const int n = wn + nt * 8 + g;
            b[nt][0] = Bsw[stage][n * 12 + tg];
            b[nt][1] = Bsw[stage][n * 12 + tg + 4];
        }
#pragma unroll
        for (int mt = 0; mt < 4; mt++)
#pragma unroll
            for (int nt = 0; nt < 4; nt++)
                mma_f16(acc[mt][nt], a[mt], b[nt]);
    }

    __half* outQK = (which == 0) ? g_qh2 : g_kh2;
#pragma unroll
    for (int mt = 0; mt < 4; mt++) {
#pragma unroll
        for (int rr = 0; rr < 2; rr++) {
            const int row = m0 + wm + mt * 16 + g + rr * 8;
            const int b_ = row / NS, s = row % NS;
#pragma unroll
            for (int nt = 0; nt < 4; nt++) {
                const int col = n0 + wn + nt * 8 + tg * 2;
                const int h = col >> 6, d = col & 63;
                const float vx = acc[mt][nt][rr * 2 + 0] + bias[col];
                const float vy = acc[mt][nt][rr * 2 + 1] + bias[col + 1];
                const size_t bh = (size_t)(b_ * NH + h);
                if (which == 2) {
                    g_vh2[(bh * HD + d)     * NS + s] = __float2half_rn(vx);
                    g_vh2[(bh * HD + d + 1) * NS + s] = __float2half_rn(vy);
                } else {
                    __half2 hv = __floats2half2_rn(vx, vy);
                    *(__half2*)&outQK[(bh * NS + s) * HD + d] = hv;
                }
            }
        }
    }
}

// ---------------- QK^T GEMM + scale + masks -> masked scores -----------------------
// grid (16 q-tiles, 16 k-tiles, 64 bh); 256 thr; CTA 128x128, K-depth 64 (one shot).
__global__ __launch_bounds__(256) void qk_kernel(const int* __restrict__ mask,
                                                 float* __restrict__ sc_arg)
{
    __shared__ __align__(16) unsigned Qs[128 * 36];
    __shared__ __align__(16) unsigned Ks[128 * 36];
    float* sc = sc_arg ? sc_arg : g_sc_fb;

    const int t = threadIdx.x;
    const int lane = t & 31, w = t >> 5;
    const int g = lane >> 2, tg = lane & 3;
    const int m0 = blockIdx.x * 128;
    const int n0 = blockIdx.y * 128;
    const int bh = blockIdx.z;
    const int b  = bh >> 4;
    const int wm = (w & 1) * 64;
    const int wn = (w >> 1) * 32;

    const __half* qb = g_qh2 + ((size_t)bh * NS + m0) * HD;
    const __half* kb = g_kh2 + ((size_t)bh * NS + n0) * HD;

    // stage both tiles via cp.async (fp16, pre-packed pairs); 8 x 16B per thread
#pragma unroll
    for (int r = 0; r < 4; r++) {
        const int idx = t + 256 * r;
        const int row = idx >> 3, c = idx & 7;
        cp16g(&Qs[row * 36 + c * 4], qb + (size_t)row * HD + c * 8);
        cp16g(&Ks[row * 36 + c * 4], kb + (size_t)row * HD + c * 8);
    }
    cp_commit(); cp_wait0();
    __syncthreads();

    float acc[4][4][4];
#pragma unroll
    for (int mt = 0; mt < 4; mt++)
#pragma unroll
        for (int nt = 0; nt < 4; nt++)
#pragma unroll
            for (int r = 0; r < 4; r++) acc[mt][nt][r] = 0.0f;

#pragma unroll
    for (int ks = 0; ks < 4; ks++) {
        unsigned a[4][4], bb[4][2];
#pragma unroll
        for (int mt = 0; mt < 4; mt++) {
            const int m = wm + mt * 16 + g;
            a[mt][0] = Qs[m * 36 + ks * 8 + tg];
            a[mt][1] = Qs[(m + 8) * 36 + ks * 8 + tg];
            a[mt][2] = Qs[m * 36 + ks * 8 + tg + 4];
            a[mt][3] = Qs[(m + 8) * 36 + ks * 8 + tg + 4];
        }
#pragma unroll
        for (int nt = 0; nt < 4; nt++) {
            const int n = wn + nt * 8 + g;
            bb[nt][0] = Ks[n * 36 + ks * 8 + tg];
            bb[nt][1] = Ks[n * 36 + ks * 8 + tg + 4];
        }
#pragma unroll
        for (int mt = 0; mt < 4; mt++)
#pragma unroll
            for (int nt = 0; nt < 4; nt++)
                mma_f16(acc[mt][nt], a[mt], bb[nt]);
    }

    // epilogue: scale + padding mask + causal mask, write masked scores
#pragma unroll
    for (int mt = 0; mt < 4; mt++) {
#pragma unroll
        for (int rr = 0; rr < 2; rr++) {
            const int qrow = m0 + wm + mt * 16 + g + rr * 8;
            const int* mrow = mask + ((size_t)b * NS + qrow) * NS;
            float* srow = sc + ((size_t)bh * NS + qrow) * NS;
#pragma unroll
            for (int nt = 0; nt < 4; nt++) {
                const int col = n0 + wn + nt * 8 + tg * 2;
                int2 mv = *(const int2*)(mrow + col);
                float sx = acc[mt][nt][rr * 2 + 0] * SCALE
                         + (1.0f - (float)mv.x) * NEGV + ((col     > qrow) ? NEGV : 0.0f);
                float sy = acc[mt][nt][rr * 2 + 1] * SCALE
                         + (1.0f - (float)mv.y) * NEGV + ((col + 1 > qrow) ? NEGV : 0.0f);
                *(float2*)(srow + col) = make_float2(sx, sy);
            }
        }
    }
}

// ---------------- row softmax in place: one warp per 2048-row ----------------------
__global__ __launch_bounds__(256) void sm_kernel(float* __restrict__ sc_arg)
{
    float* sc = sc_arg ? sc_arg : g_sc_fb;
    const int lane = threadIdx.x & 31;
    const size_t row = (size_t)blockIdx.x * 8 + (threadIdx.x >> 5);
    float* p = sc + row * NS;

    float4 v[16];
    float mx = -3.0e38f;
#pragma unroll
    for (int j = 0; j < 16; j++) {
        v[j] = *(float4*)(p + j * 128 + lane * 4);
        mx = fmaxf(mx, fmaxf(fmaxf(v[j].x, v[j].y), fmaxf(v[j].z, v[j].w)));
    }
#pragma unroll
    for (int o = 16; o > 0; o >>= 1) mx = fmaxf(mx, __shfl_xor_sync(0xffffffffu, mx, o));
    float sum = 0.0f;
#pragma unroll
    for (int j = 0; j < 16; j++) {
        v[j].x = __expf(v[j].x - mx); v[j].y = __expf(v[j].y - mx);
        v[j].z = __expf(v[j].z - mx); v[j].w = __expf(v[j].w - mx);
        sum += (v[j].x + v[j].y) + (v[j].z + v[j].w);
    }
#pragma unroll
    for (int o = 16; o > 0; o >>= 1) sum += __shfl_xor_sync(0xffffffffu, sum, o);
    const float inv = 1.0f / sum;
#pragma unroll
    for (int j = 0; j < 16; j++) {
        v[j].x *= inv; v[j].y *= inv; v[j].z *= inv; v[j].w *= inv;
        *(float4*)(p + j * 128 + lane * 4) = v[j];
    }
}

// ---------------- PV GEMM: out = P @ V -> g_ao -------------------------------------
// grid (16 m-tiles, 64 bh); 256 thr; CTA 128(M)x64(N), K-chunks 64, double-buffered.
#define PV_PW (128 * 36)
#define PV_VW (64 * 36)
#define PV_SMEM ((2 * PV_PW + 2 * PV_VW) * 4)   // 55,296 B

__global__ __launch_bounds__(256) void pv_kernel(const float* __restrict__ sc_arg)
{
    extern __shared__ __align__(16) unsigned pvs[];
    unsigned* Pw = pvs;
    unsigned* Vw = pvs + 2 * PV_PW;
    const float* sc = sc_arg ? sc_arg : g_sc_fb;

    const int t = threadIdx.x;
    const int lane = t & 31, w = t >> 5;
    const int g = lane >> 2, tg = lane & 3;
    const int m0 = blockIdx.x * 128;
    const int bh = blockIdx.y;
    const int b  = bh >> 4, h = bh & 15;
    const int wm = (w & 3) * 32;
    const int wn = (w >> 2) * 32;

    const float*  pb = sc + ((size_t)bh * NS + m0) * NS;
    const __half* vb = g_vh2 + (size_t)bh * HD * NS;

    float acc[2][4][4];
#pragma unroll
    for (int mt = 0; mt < 2; mt++)
#pragma unroll
        for (int nt = 0; nt < 4; nt++)
#pragma unroll
            for (int r = 0; r < 4; r++) acc[mt][nt][r] = 0.0f;

    int stage = 0;
    for (int k0 = 0; k0 < NS; k0 += 64, stage ^= 1) {
        unsigned* Pc = Pw + stage * PV_PW;
        unsigned* Vc = Vw + stage * PV_VW;
        // stage P [128 x 64] fp32 -> fp16 packed
#pragma unroll
        for (int r = 0; r < 8; r++) {
            const int idx = t + 256 * r;
            const int row = idx >> 4, c4 = idx & 15;
            float4 p4 = *(const float4*)(pb + (size_t)row * NS + k0 + c4 * 4);
            *(uint2*)&Pc[row * 36 + c4 * 2] =
                make_uint2(packh2(p4.x, p4.y), packh2(p4.z, p4.w));
        }
        // stage V [64 d x 64 k] fp16 transposed-global via cp.async
#pragma unroll
        for (int r = 0; r < 2; r++) {
            const int idx = t + 256 * r;
            const int d = idx >> 3, c = idx & 7;
            cp16g(&Vc[d * 36 + c * 4], vb + (size_t)d * NS + k0 + c * 8);
        }
        cp_commit(); cp_wait0();
        __syncthreads();   // single barrier/iter (skewed double buffer)
#pragma unroll
        for (int ks = 0; ks < 4; ks++) {
            unsigned a[2][4], bb[4][2];
#pragma unroll
            for (int mt = 0; mt < 2; mt++) {
                const int m = wm + mt * 16 + g;
                a[mt][0] = Pc[m * 36 + ks * 8 + tg];
                a[mt][1] = Pc[(m + 8) * 36 + ks * 8 + tg];
                a[mt][2] = Pc[m * 36 + ks * 8 + tg + 4];
                a[mt][3] = Pc[(m + 8) * 36 + ks * 8 + tg + 4];
            }
#pragma unroll
            for (int nt = 0; nt < 4; nt++) {
                const int n = wn + nt * 8 + g;
                bb[nt][0] = Vc[n * 36 + ks * 8 + tg];
                bb[nt][1] = Vc[n * 36 + ks * 8 + tg + 4];
            }
#pragma unroll
            for (int mt = 0; mt < 2; mt++)
#pragma unroll
                for (int nt = 0; nt < 4; nt++)
                    mma_f16(acc[mt][nt], a[mt], bb[nt]);
        }
    }

#pragma unroll
    for (int mt = 0; mt < 2; mt++) {
#pragma unroll
        for (int rr = 0; rr < 2; rr++) {
            const int q = m0 + wm + mt * 16 + g + rr * 8;
#pragma unroll
            for (int nt = 0; nt < 4; nt++) {
                const int d = wn + nt * 8 + tg * 2;
                float2 val = make_float2(acc[mt][nt][rr * 2 + 0], acc[mt][nt][rr * 2 + 1]);
                *(float2*)&g_ao[((size_t)b * NS + q) * ND + h * HD + d] = val;
            }
        }
    }
}

// ---------------- residual + LayerNorm, one block per (b,s) row --------------------
__global__ __launch_bounds__(256) void ln_kernel(const float* __restrict__ resid,
                                                 const float* __restrict__ gam,
                                                 const float* __restrict__ bet,
                                                 float* __restrict__ out)
{
    __shared__ float xb[ND];
    __shared__ float red[8];
    const int r = blockIdx.x;
    const int t = threadIdx.x;
    const int lane = t & 31, w = t >> 5;
    const size_t base = (size_t)r * ND;

    float lsum = 0.0f;
    for (int j = t; j < ND; j += 256) {
        const float x = g_ao[base + j] + resid[base + j];
        xb[j] = x;
        lsum += x;
    }
#pragma unroll
    for (int o = 16; o > 0; o >>= 1) lsum += __shfl_xor_sync(0xffffffffu, lsum, o);
    if (lane == 0) red[w] = lsum;
    __syncthreads();
    float tot = 0.0f;
#pragma unroll
    for (int w2 = 0; w2 < 8; w2++) tot += red[w2];
    const float mu = tot * (1.0f / ND);
    __syncthreads();

    float lv = 0.0f;
    for (int j = t; j < ND; j += 256) {
        const float dd = xb[j] - mu;
        lv += dd * dd;
    }
#pragma unroll
    for (int o = 16; o > 0; o >>= 1) lv += __shfl_xor_sync(0xffffffffu, lv, o);
    if (lane == 0) red[w] = lv;
    __syncthreads();
    float vtot = 0.0f;
#pragma unroll
    for (int w2 = 0; w2 < 8; w2++) vtot += red[w2];
    const float rstd = rsqrtf(vtot * (1.0f / ND) + 1e-5f);

    for (int j = t; j < ND; j += 256)
        out[base + j] = (xb[j] - mu) * rstd * gam[j] + bet[j];
}

// ---------------- launch -----------------------------------------------------------
extern "C" void kernel_launch(void* const* d_in, const int* in_sizes, int n_in,
                              void* d_out, int out_size)
{
    const float* q    = (const float*)d_in[0];
    const float* k    = (const float*)d_in[1];
    const float* v    = (const float*)d_in[2];
    const int*   mask = (const int*)  d_in[3];
    const float* Wq   = (const float*)d_in[4];
    const float* bq   = (const float*)d_in[5];
    const float* Wk   = (const float*)d_in[6];
    const float* bk   = (const float*)d_in[7];
    const float* Wv   = (const float*)d_in[8];
    const float* bv   = (const float*)d_in[9];
    const float* ln_g = (const float*)d_in[10];
    const float* ln_b = (const float*)d_in[11];
    float* out = (float*)d_out;

    cudaFuncSetAttribute(pv_kernel, cudaFuncAttributeMaxDynamicSharedMemorySize, PV_SMEM);

    dim3 pg(64, 8);
    proj_kernel<<<pg, 256>>>(q, Wq, bq, 0);
    proj_kernel<<<pg, 256>>>(k, Wk, bk, 1);
    proj_kernel<<<pg, 256>>>(v, Wv, bv, 2);

    float* attn = nullptr;
    const long long need = (long long)NB * NS * ND + (long long)NB * NH * NS * NS;
    if ((long long)out_size >= need) attn = out + (size_t)NB * NS * ND;

    qk_kernel<<<dim3(NS / 128, NS / 128, NB * NH), 256>>>(mask, attn);
    sm_kernel<<<(NB * NH * NS) / 8, 256>>>(attn);
    pv_kernel<<<dim3(NS / 128, NB * NH), 256, PV_SMEM>>>(attn);
    ln_kernel<<<NB * NS, 256>>>(q, ln_g, ln_b, out);
}